// round 11
// baseline (speedup 1.0000x reference)
#include <cuda_runtime.h>
#include <cuda_bf16.h>
#include <stdint.h>

#define EPSF 1e-6f
#define TPB 256
#define SPB 64                    // samples per block
#define WPS 30                    // uint32 words per 120B mask row
#define VPB (SPB * WPS / 4)       // 480 uint4 per block
#define MAX_PART 8192

__device__ float g_part[MAX_PART];
__device__ unsigned int g_ticket = 0;   // reset by last block every call

// ---------------- fused kernel: 64 samples/block, H = 120, B % 64 == 0 ----------------
__global__ void __launch_bounds__(TPB) runway_loss_h120(
        const float* __restrict__ pred,
        const unsigned char* __restrict__ mask,
        const float* __restrict__ runway,
        float* __restrict__ out,
        int B) {
    const unsigned FULL = 0xFFFFFFFFu;
    __shared__ int   s_ones[SPB];
    __shared__ float s_win[SPB][16];        // 64B gather window per sample
    __shared__ float s_wsum[TPB / 32];

    int tid = threadIdx.x;
    int ls  = tid >> 2;                     // local sample 0..63
    int sub = tid & 3;                      // lane within 4-lane group
    int s   = blockIdx.x * SPB + ls;        // global sample

    if (tid < SPB) s_ones[tid] = 0;

    // front-batch runway dir (independent of mask)
    float2 rdir = *(const float2*)(runway + (size_t)s * 4 + 2);
    __syncthreads();

    // ---- phase A: fully-coalesced uint4 mask stream, popc into s_ones ----
    const uint4* mv = (const uint4*)mask + (size_t)blockIdx.x * VPB;
    #pragma unroll
    for (int it = 0; it < 2; it++) {
        int v = tid + it * TPB;
        if (v < VPB) {
            uint4 u = mv[v];
            int pc0 = __popc(u.x), pc1 = __popc(u.y);
            int pc2 = __popc(u.z), pc3 = __popc(u.w);
            int wb = v * 4;                 // block-local word index
            int sA = wb / 30;
            int sB = (wb + 3) / 30;
            int tot = pc0 + pc1 + pc2 + pc3;
            if (sA == sB) {
                atomicAdd(&s_ones[sA], tot);
            } else {
                int k = sB * 30 - wb;       // words belonging to sA (1..3)
                int sumA = pc0;
                if (k > 1) sumA += pc1;
                if (k > 2) sumA += pc2;
                atomicAdd(&s_ones[sA], sumA);
                atomicAdd(&s_ones[sB], tot - sumA);
            }
        }
    }
    __syncthreads();

    // ---- phase B: one LDG.128 per lane covers the 4-point window ----
    int L  = 120 - s_ones[ls];              // valid length, in [5,120]
    int f0 = 3 * (L - 4);                   // first float of point L-4
    int W0 = f0 & ~3;                       // 16B-aligned window start
    if (W0 > 344) W0 = 344;                 // keep window inside the 360-float row
    const float* prow = pred + (size_t)s * 360;
    float4 w = *(const float4*)(prow + W0 + sub * 4);
    *(float4*)&s_win[ls][sub * 4] = w;
    __syncwarp();

    int ob = f0 - W0;                       // 0..4
    const float* wrow = s_win[ls];
    float term = 0.0f;
    if (sub < 3) {
        float ax = wrow[ob + 3 * sub];
        float ay = wrow[ob + 3 * sub + 1];
        float bx = wrow[ob + 3 * sub + 3];
        float by = wrow[ob + 3 * sub + 4];

        float rx = rdir.x, ry = rdir.y;
        float rn = sqrtf(rx * rx + ry * ry) + EPSF;
        rx /= rn; ry /= rn;

        float dx = bx - ax;
        float dy = by - ay;
        float dn = sqrtf(dx * dx + dy * dy) + EPSF;
        float cs = (dx / dn) * rx + (dy / dn) * ry;
        float u  = 1.0f - cs;
        term = u * u;
    }
    term += __shfl_xor_sync(FULL, term, 1);
    term += __shfl_xor_sync(FULL, term, 2);
    float per = (sub == 0) ? term * (1.0f / 3.0f) : 0.0f;

    // warp reduce
    per += __shfl_xor_sync(FULL, per, 4);
    per += __shfl_xor_sync(FULL, per, 8);
    per += __shfl_xor_sync(FULL, per, 16);

    int lane = tid & 31, wid = tid >> 5;
    if (lane == 0) s_wsum[wid] = per;
    __syncthreads();

    __shared__ bool s_last;
    if (tid == 0) {
        float bsum = 0.0f;
        #pragma unroll
        for (int i = 0; i < TPB / 32; i++) bsum += s_wsum[i];
        g_part[blockIdx.x] = bsum;
        __threadfence();
        unsigned int tkt = atomicAdd(&g_ticket, 1u);
        s_last = (tkt == gridDim.x - 1);
    }
    __syncthreads();

    if (s_last) {
        __threadfence();                    // acquire all g_part writes
        __shared__ double dred[TPB];
        double dv = 0.0;
        for (int i = tid; i < (int)gridDim.x; i += TPB)
            dv += (double)g_part[i];
        dred[tid] = dv;
        __syncthreads();
        #pragma unroll
        for (int o = TPB / 2; o >= 1; o >>= 1) {
            if (tid < o) dred[tid] += dred[tid + o];
            __syncthreads();
        }
        if (tid == 0) {
            out[0] = (float)(dred[0] / (double)B);
            g_ticket = 0;
        }
    }
}

// ---------------- generic fallback (thread-per-sample, single launch) ----------------
__global__ void __launch_bounds__(TPB) runway_loss_generic(
        const float* __restrict__ pred,
        const unsigned char* __restrict__ mask,
        const float* __restrict__ runway,
        float* __restrict__ out,
        int B, int H) {
    int s = blockIdx.x * blockDim.x + threadIdx.x;
    float contrib = 0.0f;
    if (s < B) {
        const unsigned char* mrow = mask + (size_t)s * H;
        int ones = 0;
        for (int i = 0; i < H; i++) ones += (int)mrow[i];
        int L = H - ones;
        float rx = runway[(size_t)s * 4 + 2];
        float ry = runway[(size_t)s * 4 + 3];
        float rn = sqrtf(rx * rx + ry * ry) + EPSF;
        rx /= rn; ry /= rn;
        const float* prow = pred + (size_t)s * H * 3;
        float px[4], py[4];
        for (int j = 0; j < 4; j++) {
            int idx = L - 4 + j;
            if (idx < 0) idx = 0;
            if (idx > H - 1) idx = H - 1;
            px[j] = prow[idx * 3 + 0];
            py[j] = prow[idx * 3 + 1];
        }
        float acc = 0.0f;
        for (int j = 0; j < 3; j++) {
            float dx = px[j + 1] - px[j];
            float dy = py[j + 1] - py[j];
            float dn = sqrtf(dx * dx + dy * dy) + EPSF;
            float cs = (dx / dn) * rx + (dy / dn) * ry;
            float u  = 1.0f - cs;
            acc += u * u;
        }
        contrib = acc * (1.0f / 3.0f);
    }
    __shared__ float red[TPB];
    red[threadIdx.x] = contrib;
    __syncthreads();
    for (int o = TPB / 2; o >= 32; o >>= 1) {
        if (threadIdx.x < o) red[threadIdx.x] += red[threadIdx.x + o];
        __syncthreads();
    }
    __shared__ bool s_last;
    if (threadIdx.x < 32) {
        float v = red[threadIdx.x];
        for (int o = 16; o; o >>= 1)
            v += __shfl_xor_sync(0xFFFFFFFFu, v, o);
        if (threadIdx.x == 0) {
            g_part[blockIdx.x] = v;
            __threadfence();
            unsigned int tkt = atomicAdd(&g_ticket, 1u);
            s_last = (tkt == gridDim.x - 1);
        }
    }
    __syncthreads();
    if (s_last) {
        __threadfence();
        __shared__ double dred[TPB];
        double dv = 0.0;
        for (int i = threadIdx.x; i < (int)gridDim.x; i += TPB)
            dv += (double)g_part[i];
        dred[threadIdx.x] = dv;
        __syncthreads();
        for (int o = TPB / 2; o >= 1; o >>= 1) {
            if (threadIdx.x < o) dred[threadIdx.x] += dred[threadIdx.x + o];
            __syncthreads();
        }
        if (threadIdx.x == 0) {
            out[0] = (float)(dred[0] / (double)B);
            g_ticket = 0;
        }
    }
}

extern "C" void kernel_launch(void* const* d_in, const int* in_sizes, int n_in,
                              void* d_out, int out_size) {
    const float*         pred   = (const float*)d_in[0];
    // d_in[1] = target_abs (unused by the reference)
    const unsigned char* mask   = (const unsigned char*)d_in[2];
    const float*         runway = (const float*)d_in[3];
    float*               out    = (float*)d_out;

    int B = in_sizes[3] / 4;          // runway is (B, 4)
    int H = in_sizes[2] / B;          // mask is (B, H)

    if (H == 120 && (B % SPB) == 0 && B / SPB <= MAX_PART) {
        int blocks = B / SPB;         // 65536 -> 1024 blocks
        runway_loss_h120<<<blocks, TPB>>>(pred, mask, runway, out, B);
    } else {
        int blocks = (B + TPB - 1) / TPB;
        if (blocks > MAX_PART) blocks = MAX_PART;
        runway_loss_generic<<<blocks, TPB>>>(pred, mask, runway, out, B, H);
    }
}